// round 16
// baseline (speedup 1.0000x reference)
#include <cuda_runtime.h>
#include <cuda_fp16.h>

#define N_USERS   50000
#define N_ITEMS   30000
#define N_ENT     100000
#define N_REL     50
#define N_EDGES   1500000
#define N_INTER   1000000
#define D         64
#define GAMMA_F   0.1f
#define FULLMASK  0xffffffffu

#define PB0 49   // ceil(N_ENT/2048)
#define PB1 25   // ceil(N_USERS/2048)
#define PB2 15   // ceil(N_ITEMS/2048)
#define PBT (PB0 + PB1 + PB2)

// ---------------- static device scratch ----------------
__device__ int   g_bins_e[N_ENT];
__device__ int   g_bins_r[N_USERS];
__device__ int   g_bins_c[N_ITEMS];
__device__ int   g_cur_e[N_ENT];
__device__ int   g_cur_r[N_USERS];
__device__ int   g_cur_c[N_ITEMS];
__device__ int   g_eoff[N_ENT + 1];
__device__ int   g_roff[N_USERS + 1];
__device__ int   g_coff[N_ITEMS + 1];
__device__ int   g_part[PBT];
__device__ int   g_tp[N_EDGES];          // packed tail | (rel<<17)
__device__ int2  g_rc[N_INTER];          // (col, orig idx)
__device__ int   g_crow[N_INTER];
__device__ int   g_rhist[N_ITEMS * N_REL];
__device__ float g_W1t[D * D];
__device__ float g_W2t[D * D];
__device__ uint2 g_wkg_h[N_ITEMS * 16];  // fp16 wkg rows
__device__ uint2 g_icf_h[N_ITEMS * 16];  // fp16 icf rows
__device__ float g_cu[N_INTER];          // slow path only
__device__ float g_cc[N_INTER];

__device__ __forceinline__ float fsigmoid(float x) {
    return __fdividef(1.f, 1.f + __expf(-x));
}

__device__ __forceinline__ uint2 pack_h4(float a, float b, float c, float d) {
    __half2 h0 = __floats2half2_rn(a, b);
    __half2 h1 = __floats2half2_rn(c, d);
    uint2 pk;
    pk.x = *(unsigned*)&h0;
    pk.y = *(unsigned*)&h1;
    return pk;
}

// ---------------- edge chain setup ----------------
__global__ void zeroER_kernel(const float* __restrict__ W1, const float* __restrict__ W2) {
    int i = blockIdx.x * blockDim.x + threadIdx.x;
    if (i < N_ENT) g_bins_e[i] = 0;
    if (i < N_ITEMS * N_REL) g_rhist[i] = 0;
    if (i < D * D) {
        int d = i >> 6, k = i & 63;
        g_W1t[(k << 6) + d] = W1[i];
        g_W2t[(k << 6) + d] = W2[i];
    }
}

__global__ void histER_kernel(const int* __restrict__ head,
                              const int* __restrict__ etype) {
    int i = blockIdx.x * blockDim.x + threadIdx.x;
    if (i < N_EDGES) {
        int h = head[i];
        atomicAdd(&g_bins_e[h], 1);
        if (h < N_ITEMS) atomicAdd(&g_rhist[h * N_REL + etype[i]], 1);
    }
}

__global__ void scatterE_kernel(const int* __restrict__ head,
                                const int* __restrict__ tail,
                                const int* __restrict__ etype) {
    int i = blockIdx.x * blockDim.x + threadIdx.x;
    if (i < N_EDGES) {
        int h = head[i];
        int pos = atomicAdd(&g_cur_e[h], 1);
        g_tp[pos] = tail[i] | (etype[i] << 17);
    }
}

// warp handles 2 items: wkg = (hist @ relw / deg) * ent, stored fp16
__global__ void __launch_bounds__(256) wkg_kernel(
    const float* __restrict__ ent, const float* __restrict__ relw)
{
    __shared__ float sRel[N_REL * D];
    int tid = threadIdx.x;
    for (int i = tid; i < N_REL * D; i += 256) sRel[i] = relw[i];
    __syncthreads();

    int warp = tid >> 5, lane = tid & 31, hl = lane >> 4, q = lane & 15;
    int h = blockIdx.x * 16 + warp * 2 + hl;   // 1875*16 = 30000 exact
    float4 acc = make_float4(0.f, 0.f, 0.f, 0.f);
    int deg = 0;
    #pragma unroll 5
    for (int r = 0; r < N_REL; r++) {
        int cnt = g_rhist[h * N_REL + r];
        deg += cnt;
        if (cnt) {
            float fc = (float)cnt;
            float4 w = *(const float4*)&sRel[r * D + q * 4];
            acc.x += fc * w.x; acc.y += fc * w.y;
            acc.z += fc * w.z; acc.w += fc * w.w;
        }
    }
    float inv = 1.f / fmaxf((float)deg, 1.f);
    float4 kg = *(const float4*)&ent[(size_t)h * D + q * 4];
    g_wkg_h[h * 16 + q] = pack_h4(acc.x * inv * kg.x, acc.y * inv * kg.y,
                                  acc.z * inv * kg.z, acc.w * inv * kg.w);
}

// ---------------- inter chain setup ----------------
__global__ void zeroI_kernel() {
    int i = blockIdx.x * blockDim.x + threadIdx.x;
    if (i < N_USERS) g_bins_r[i] = 0;
    if (i < N_ITEMS) g_bins_c[i] = 0;
}

// histI + icf fp16 conversion fused (same pass; conversion is independent work)
__global__ void histI_kernel(const int2* __restrict__ imat,
                             const float* __restrict__ icf) {
    int i = blockIdx.x * blockDim.x + threadIdx.x;
    if (i < N_INTER) {
        int2 rc = imat[i];
        atomicAdd(&g_bins_r[rc.x], 1);
        atomicAdd(&g_bins_c[rc.y], 1);
    }
    if (i < N_ITEMS * 16) {
        float4 v = ((const float4*)icf)[i];
        g_icf_h[i] = pack_h4(v.x, v.y, v.z, v.w);
    }
}

__global__ void scatterI_kernel(const int2* __restrict__ imat) {
    int i = blockIdx.x * blockDim.x + threadIdx.x;
    if (i < N_INTER) {
        int2 rc = imat[i];
        int pr = atomicAdd(&g_cur_r[rc.x], 1);
        g_rc[pr] = make_int2(rc.y, i);
        int pc = atomicAdd(&g_cur_c[rc.y], 1);
        g_crow[pc] = rc.x;
    }
}

// ---------------- 2-phase multi-block scan ----------------
__device__ __forceinline__ void scan_map(int b, int& which, int& lb) {
    which = (b < PB0) ? 0 : (b < PB0 + PB1) ? 1 : 2;
    lb = b - ((which == 0) ? 0 : (which == 1) ? PB0 : PB0 + PB1);
}

__global__ void __launch_bounds__(256) scanA_kernel(int base_blk) {
    int b = blockIdx.x + base_blk;
    int which, lb;
    scan_map(b, which, lb);
    int n = (which == 0) ? N_ENT : (which == 1) ? N_USERS : N_ITEMS;
    const int* bins = (which == 0) ? g_bins_e : (which == 1) ? g_bins_r : g_bins_c;
    int base = lb * 2048;
    int sum = 0;
    for (int i = threadIdx.x; i < 2048; i += 256) {
        int idx = base + i;
        sum += (idx < n) ? bins[idx] : 0;
    }
    #pragma unroll
    for (int o = 16; o; o >>= 1) sum += __shfl_xor_sync(FULLMASK, sum, o);
    __shared__ int ws[8];
    int lane = threadIdx.x & 31, wid = threadIdx.x >> 5;
    if (lane == 0) ws[wid] = sum;
    __syncthreads();
    if (threadIdx.x == 0) {
        int t = 0;
        #pragma unroll
        for (int i = 0; i < 8; i++) t += ws[i];
        g_part[b] = t;
    }
}

__global__ void __launch_bounds__(256) scanC_kernel(int base_blk) {
    int b = blockIdx.x + base_blk;
    int which, lb;
    scan_map(b, which, lb);
    int n  = (which == 0) ? N_ENT : (which == 1) ? N_USERS : N_ITEMS;
    int nb = (which == 0) ? PB0   : (which == 1) ? PB1     : PB2;
    int pbase = (which == 0) ? 0  : (which == 1) ? PB0     : PB0 + PB1;
    const int* bins = (which == 0) ? g_bins_e : (which == 1) ? g_bins_r : g_bins_c;
    int* offs = (which == 0) ? g_eoff : (which == 1) ? g_roff : g_coff;
    int* cur  = (which == 0) ? g_cur_e : (which == 1) ? g_cur_r : g_cur_c;
    int base = lb * 2048;
    int lane = threadIdx.x & 31, wid = threadIdx.x >> 5;

    __shared__ int s_pref;
    if (wid == 0) {
        int p = 0;
        for (int i = lane; i < lb; i += 32) p += g_part[pbase + i];
        #pragma unroll
        for (int o = 16; o; o >>= 1) p += __shfl_xor_sync(FULLMASK, p, o);
        if (lane == 0) {
            s_pref = p;
            if (lb == nb - 1) offs[n] = p + g_part[pbase + lb];
        }
    }

    int vals[8];
    int tsum = 0;
    #pragma unroll
    for (int k = 0; k < 8; k++) {
        int idx = base + threadIdx.x * 8 + k;
        vals[k] = (idx < n) ? bins[idx] : 0;
        tsum += vals[k];
    }
    int x = tsum;
    #pragma unroll
    for (int o = 1; o < 32; o <<= 1) {
        int t = __shfl_up_sync(FULLMASK, x, o);
        if (lane >= o) x += t;
    }
    __shared__ int ws[8];
    if (lane == 31) ws[wid] = x;
    __syncthreads();
    int wpref = 0;
    for (int i = 0; i < wid; i++) wpref += ws[i];
    int acc = s_pref + wpref + x - tsum;
    #pragma unroll
    for (int k = 0; k < 8; k++) {
        int idx = base + threadIdx.x * 8 + k;
        if (idx < n) { offs[idx] = acc; cur[idx] = acc; }
        acc += vals[k];
    }
}

// ---------------- KG aggregation: 2 entities per warp ----------------
#define EBLK 6250

__global__ void __launch_bounds__(256) entity_kernel(
    const float* __restrict__ ent, const float* __restrict__ relw,
    const float* __restrict__ b1, const float* __restrict__ b2,
    float* __restrict__ out_agg)
{
    __shared__ float sRel[N_REL * D];
    __shared__ float sMA[8][2][D];
    __shared__ float sMB[8][2][D];
    int tid = threadIdx.x;
    for (int i = tid; i < N_REL * D; i += 256) sRel[i] = relw[i];
    __syncthreads();

    int warp = tid >> 5, lane = tid & 31, hl = lane >> 4, q = lane & 15;
    int h = blockIdx.x * 16 + warp * 2 + hl;
    int s = g_eoff[h], e = g_eoff[h + 1];
    bool head_item = (h < N_ITEMS);

    float4 a1 = make_float4(0.f, 0.f, 0.f, 0.f), a2 = a1;
    int c1 = 0, c2 = 0;
    #pragma unroll 2
    for (int j = s; j < e; j++) {
        int v = g_tp[j];
        int t = v & 0x1FFFF;
        int r = v >> 17;
        float4 te = *(const float4*)&ent[(size_t)t * D + q * 4];
        float4 re = *(const float4*)&sRel[r * D + q * 4];
        bool cross = head_item ^ (t < N_ITEMS);
        if (cross) {
            a1.x += te.x * re.x; a1.y += te.y * re.y;
            a1.z += te.z * re.z; a1.w += te.w * re.w; c1++;
        } else {
            a2.x += te.x + re.x; a2.y += te.y + re.y;
            a2.z += te.z + re.z; a2.w += te.w + re.w; c2++;
        }
    }
    float inv1 = 1.f / fmaxf((float)c1, 1.f);
    float inv2 = 1.f / fmaxf((float)c2, 1.f);

    *(float4*)&sMA[warp][hl][q * 4] = make_float4(a1.x * inv1, a1.y * inv1, a1.z * inv1, a1.w * inv1);
    *(float4*)&sMB[warp][hl][q * 4] = make_float4(a2.x * inv2, a2.y * inv2, a2.z * inv2, a2.w * inv2);
    __syncwarp();

    float4 o = *(const float4*)&b1[q * 4];
    float4 p = *(const float4*)&b2[q * 4];
    #pragma unroll 8
    for (int k = 0; k < D; k++) {
        float m1 = sMA[warp][hl][k];
        float m2 = sMB[warp][hl][k];
        float4 w1 = *(const float4*)&g_W1t[k * D + q * 4];
        float4 w2 = *(const float4*)&g_W2t[k * D + q * 4];
        o.x += m1 * w1.x; o.y += m1 * w1.y; o.z += m1 * w1.z; o.w += m1 * w1.w;
        p.x += m2 * w2.x; p.y += m2 * w2.y; p.z += m2 * w2.z; p.w += m2 * w2.w;
    }
    float4 r;
    r.x = (o.x >= 0.f ? o.x : 0.01f * o.x) * 0.5f + (p.x >= 0.f ? p.x : 0.01f * p.x) * 0.5f;
    r.y = (o.y >= 0.f ? o.y : 0.01f * o.y) * 0.5f + (p.y >= 0.f ? p.y : 0.01f * p.y) * 0.5f;
    r.z = (o.z >= 0.f ? o.z : 0.01f * o.z) * 0.5f + (p.z >= 0.f ? p.z : 0.01f * p.z) * 0.5f;
    r.w = (o.w >= 0.f ? o.w : 0.01f * o.w) * 0.5f + (p.w >= 0.f ? p.w : 0.01f * p.w) * 0.5f;
    *(float4*)&out_agg[(size_t)h * D + q * 4] = r;
}

// ---------------- item_agg: warp per item ----------------
__global__ void __launch_bounds__(256) item_kernel(
    const float* __restrict__ ucf0, float* __restrict__ out_item)
{
    int warp = threadIdx.x >> 5, lane = threadIdx.x & 31;
    int hl = lane >> 4, q = lane & 15;
    int it = blockIdx.x * 8 + warp;
    int s = g_coff[it], e = g_coff[it + 1];
    float4 acc = make_float4(0.f, 0.f, 0.f, 0.f);
    int j = s;
    #pragma unroll 2
    for (; j + 2 <= e; j += 2) {
        int r = g_crow[j + hl];
        float4 v = *(const float4*)&ucf0[(size_t)r * D + q * 4];
        acc.x += v.x; acc.y += v.y; acc.z += v.z; acc.w += v.w;
    }
    if (j < e && hl == 0) {
        int r = g_crow[j];
        float4 v = *(const float4*)&ucf0[(size_t)r * D + q * 4];
        acc.x += v.x; acc.y += v.y; acc.z += v.z; acc.w += v.w;
    }
    acc.x += __shfl_xor_sync(FULLMASK, acc.x, 16);
    acc.y += __shfl_xor_sync(FULLMASK, acc.y, 16);
    acc.z += __shfl_xor_sync(FULLMASK, acc.z, 16);
    acc.w += __shfl_xor_sync(FULLMASK, acc.w, 16);
    if (hl == 0) {
        float inv = 1.f / fmaxf((float)(e - s), 1.f);
        float4 r = make_float4(acc.x * inv, acc.y * inv, acc.z * inv, acc.w * inv);
        *(float4*)&out_item[(size_t)it * D + q * 4] = r;
    }
}

// ---------------- fused 3-iteration CF attention (register + smem dots) ----------------
__global__ void __launch_bounds__(256) iter3_kernel(
    const float* __restrict__ user, const float* __restrict__ ucf0,
    const float* __restrict__ ent,  const float* __restrict__ icf,
    float* __restrict__ out_u, float* __restrict__ out_ucf,
    float* __restrict__ out_mask)
{
    __shared__ float sd1[8][32];
    __shared__ float sd2[8][32];
    int warp = threadIdx.x >> 5, lane = threadIdx.x & 31;
    int hl = lane >> 4, q = lane & 15;

    int gw = blockIdx.x * 8 + warp;
    int s = g_roff[gw], e = g_roff[gw + 1];
    int deg = e - s;

    float4 u = *(const float4*)&user[(size_t)gw * D + q * 4];
    float4 c = *(const float4*)&ucf0[(size_t)gw * D + q * 4];

    if (deg <= 32) {
        // ======== FAST PATH ========
        int2 rcme = make_int2(0, 0);
        if (lane < deg) rcme = g_rc[s + lane];
        int colme = rcme.x;

        #pragma unroll 1
        for (int it = 0; it < 3; it++) {
            // ---- pass 1: dots -> smem slots ----
            for (int l0 = 0; l0 < deg; l0 += 2) {
                int a = l0 + hl;
                int aa = (a < deg) ? a : l0;
                int col = __shfl_sync(FULLMASK, colme, aa);
                uint2 wr = g_wkg_h[(size_t)col * 16 + q];
                uint2 vr = g_icf_h[(size_t)col * 16 + q];
                float2 wa = __half22float2(*(__half2*)&wr.x);
                float2 wb = __half22float2(*(__half2*)&wr.y);
                float2 va = __half22float2(*(__half2*)&vr.x);
                float2 vb = __half22float2(*(__half2*)&vr.y);
                float d1 = u.x * wa.x + u.y * wa.y + u.z * wb.x + u.w * wb.y;
                float d2 = c.x * va.x + c.y * va.y + c.z * vb.x + c.w * vb.y;
                #pragma unroll
                for (int o = 8; o; o >>= 1) {
                    d1 += __shfl_xor_sync(FULLMASK, d1, o);
                    d2 += __shfl_xor_sync(FULLMASK, d2, o);
                }
                if (q == 0 && a < deg) {
                    sd1[warp][a] = d1;
                    sd2[warp][a] = d2;
                }
            }
            __syncwarp();
            float epu = 0.f, epc = 0.f;
            if (lane < deg) {
                epu = __expf(fsigmoid(sd1[warp][lane]));
                epc = __expf(fsigmoid(sd2[warp][lane]));
            }
            float z = epu, zc = epc;
            #pragma unroll
            for (int o = 16; o; o >>= 1) {
                z  += __shfl_xor_sync(FULLMASK, z, o);
                zc += __shfl_xor_sync(FULLMASK, zc, o);
            }
            float iz  = (z  > 0.f) ? __fdividef(1.f, z)  : 0.f;
            float izc = (zc > 0.f) ? __fdividef(1.f, zc) : 0.f;
            float pn = epu * iz, qn = epc * izc;
            float m = (fabsf(fsigmoid(pn) - fsigmoid(qn)) < GAMMA_F) ? 1.f : 0.f;
            float coefu = pn * m, coefc = qn * m;
            if (it == 2 && lane < deg) out_mask[rcme.y] = m;

            // ---- pass 2: weighted sums (fp32) ----
            float4 au = make_float4(0.f, 0.f, 0.f, 0.f), ac = au;
            #pragma unroll 2
            for (int l0 = 0; l0 < deg; l0 += 2) {
                int a = l0 + hl;
                int aa = (a < deg) ? a : l0;
                int col = __shfl_sync(FULLMASK, colme, aa);
                float cu = __shfl_sync(FULLMASK, coefu, aa);
                float cc = __shfl_sync(FULLMASK, coefc, aa);
                if (a >= deg) { cu = 0.f; cc = 0.f; }
                float4 kg = *(const float4*)&ent[(size_t)col * D + q * 4];
                float4 v  = *(const float4*)&icf[(size_t)col * D + q * 4];
                au.x += cu * kg.x; au.y += cu * kg.y; au.z += cu * kg.z; au.w += cu * kg.w;
                ac.x += cc * v.x;  ac.y += cc * v.y;  ac.z += cc * v.z;  ac.w += cc * v.w;
            }
            au.x += __shfl_xor_sync(FULLMASK, au.x, 16);
            au.y += __shfl_xor_sync(FULLMASK, au.y, 16);
            au.z += __shfl_xor_sync(FULLMASK, au.z, 16);
            au.w += __shfl_xor_sync(FULLMASK, au.w, 16);
            ac.x += __shfl_xor_sync(FULLMASK, ac.x, 16);
            ac.y += __shfl_xor_sync(FULLMASK, ac.y, 16);
            ac.z += __shfl_xor_sync(FULLMASK, ac.z, 16);
            ac.w += __shfl_xor_sync(FULLMASK, ac.w, 16);

            if (it < 2) {
                float su = au.x * au.x + au.y * au.y + au.z * au.z + au.w * au.w;
                float sc = ac.x * ac.x + ac.y * ac.y + ac.z * ac.z + ac.w * ac.w;
                #pragma unroll
                for (int o = 8; o; o >>= 1) {
                    su += __shfl_xor_sync(FULLMASK, su, o);
                    sc += __shfl_xor_sync(FULLMASK, sc, o);
                }
                float inu = __fdividef(1.f, fmaxf(sqrtf(su), 1e-12f));
                float inc = __fdividef(1.f, fmaxf(sqrtf(sc), 1e-12f));
                u.x = au.x * inu; u.y = au.y * inu; u.z = au.z * inu; u.w = au.w * inu;
                c.x = ac.x * inc; c.y = ac.y * inc; c.z = ac.z * inc; c.w = ac.w * inc;
            } else if (hl == 0) {
                *(float4*)&out_u[(size_t)gw * D + q * 4]   = au;
                *(float4*)&out_ucf[(size_t)gw * D + q * 4] = ac;
            }
            __syncwarp();
        }
        return;
    }

    // ======== SLOW PATH (deg > 32) ========
    #pragma unroll 1
    for (int it = 0; it < 3; it++) {
        float z = 0.f, zc = 0.f;
        int j = s;
        for (; j + 2 <= e; j += 2) {
            int col = g_rc[j + hl].x;
            uint2 wr = g_wkg_h[(size_t)col * 16 + q];
            uint2 vr = g_icf_h[(size_t)col * 16 + q];
            float2 wa = __half22float2(*(__half2*)&wr.x);
            float2 wb = __half22float2(*(__half2*)&wr.y);
            float2 va = __half22float2(*(__half2*)&vr.x);
            float2 vb = __half22float2(*(__half2*)&vr.y);
            float d1 = u.x * wa.x + u.y * wa.y + u.z * wb.x + u.w * wb.y;
            float d2 = c.x * va.x + c.y * va.y + c.z * vb.x + c.w * vb.y;
            #pragma unroll
            for (int o = 8; o; o >>= 1) {
                d1 += __shfl_xor_sync(FULLMASK, d1, o);
                d2 += __shfl_xor_sync(FULLMASK, d2, o);
            }
            if (q == 0) {
                float ep = __expf(fsigmoid(d1));
                float eq = __expf(fsigmoid(d2));
                z += ep; zc += eq;
                g_cu[j + hl] = ep;
                g_cc[j + hl] = eq;
            }
        }
        if (j < e) {
            int col = g_rc[j].x;
            uint2 wr = g_wkg_h[(size_t)col * 16 + q];
            uint2 vr = g_icf_h[(size_t)col * 16 + q];
            float2 wa = __half22float2(*(__half2*)&wr.x);
            float2 wb = __half22float2(*(__half2*)&wr.y);
            float2 va = __half22float2(*(__half2*)&vr.x);
            float2 vb = __half22float2(*(__half2*)&vr.y);
            float d1 = u.x * wa.x + u.y * wa.y + u.z * wb.x + u.w * wb.y;
            float d2 = c.x * va.x + c.y * va.y + c.z * vb.x + c.w * vb.y;
            #pragma unroll
            for (int o = 8; o; o >>= 1) {
                d1 += __shfl_xor_sync(FULLMASK, d1, o);
                d2 += __shfl_xor_sync(FULLMASK, d2, o);
            }
            if (lane == 0) {
                float ep = __expf(fsigmoid(d1));
                float eq = __expf(fsigmoid(d2));
                z += ep; zc += eq;
                g_cu[j] = ep;
                g_cc[j] = eq;
            }
        }
        __syncwarp();
        #pragma unroll
        for (int o = 16; o; o >>= 1) {
            z  += __shfl_xor_sync(FULLMASK, z, o);
            zc += __shfl_xor_sync(FULLMASK, zc, o);
        }
        float iz  = (z  > 0.f) ? __fdividef(1.f, z)  : 0.f;
        float izc = (zc > 0.f) ? __fdividef(1.f, zc) : 0.f;

        for (int jj = s + lane; jj < e; jj += 32) {
            float pn = g_cu[jj] * iz;
            float qn = g_cc[jj] * izc;
            float m = (fabsf(fsigmoid(pn) - fsigmoid(qn)) < GAMMA_F) ? 1.f : 0.f;
            if (it == 2) out_mask[g_rc[jj].y] = m;
            g_cu[jj] = pn * m;
            g_cc[jj] = qn * m;
        }
        __syncwarp();

        float4 au = make_float4(0.f, 0.f, 0.f, 0.f), ac = au;
        j = s;
        for (; j + 2 <= e; j += 2) {
            int jj = j + hl;
            int col = g_rc[jj].x;
            float cu = g_cu[jj], cc = g_cc[jj];
            float4 kg = *(const float4*)&ent[(size_t)col * D + q * 4];
            float4 v  = *(const float4*)&icf[(size_t)col * D + q * 4];
            au.x += cu * kg.x; au.y += cu * kg.y; au.z += cu * kg.z; au.w += cu * kg.w;
            ac.x += cc * v.x;  ac.y += cc * v.y;  ac.z += cc * v.z;  ac.w += cc * v.w;
        }
        if (j < e && hl == 0) {
            int col = g_rc[j].x;
            float cu = g_cu[j], cc = g_cc[j];
            float4 kg = *(const float4*)&ent[(size_t)col * D + q * 4];
            float4 v  = *(const float4*)&icf[(size_t)col * D + q * 4];
            au.x += cu * kg.x; au.y += cu * kg.y; au.z += cu * kg.z; au.w += cu * kg.w;
            ac.x += cc * v.x;  ac.y += cc * v.y;  ac.z += cc * v.z;  ac.w += cc * v.w;
        }
        au.x += __shfl_xor_sync(FULLMASK, au.x, 16);
        au.y += __shfl_xor_sync(FULLMASK, au.y, 16);
        au.z += __shfl_xor_sync(FULLMASK, au.z, 16);
        au.w += __shfl_xor_sync(FULLMASK, au.w, 16);
        ac.x += __shfl_xor_sync(FULLMASK, ac.x, 16);
        ac.y += __shfl_xor_sync(FULLMASK, ac.y, 16);
        ac.z += __shfl_xor_sync(FULLMASK, ac.z, 16);
        ac.w += __shfl_xor_sync(FULLMASK, ac.w, 16);

        if (it < 2) {
            float su = au.x * au.x + au.y * au.y + au.z * au.z + au.w * au.w;
            float sc = ac.x * ac.x + ac.y * ac.y + ac.z * ac.z + ac.w * ac.w;
            #pragma unroll
            for (int o = 8; o; o >>= 1) {
                su += __shfl_xor_sync(FULLMASK, su, o);
                sc += __shfl_xor_sync(FULLMASK, sc, o);
            }
            float inu = __fdividef(1.f, fmaxf(sqrtf(su), 1e-12f));
            float inc = __fdividef(1.f, fmaxf(sqrtf(sc), 1e-12f));
            u.x = au.x * inu; u.y = au.y * inu; u.z = au.z * inu; u.w = au.w * inu;
            c.x = ac.x * inc; c.y = ac.y * inc; c.z = ac.z * inc; c.w = ac.w * inc;
        } else if (hl == 0) {
            *(float4*)&out_u[(size_t)gw * D + q * 4]   = au;
            *(float4*)&out_ucf[(size_t)gw * D + q * 4] = ac;
        }
        __syncwarp();
    }
}

// ---------------- launch: dependency-ordered fork (R9 structure) ----------------
extern "C" void kernel_launch(void* const* d_in, const int* in_sizes, int n_in,
                              void* d_out, int out_size) {
    const float* ent   = (const float*)d_in[0];
    const float* user  = (const float*)d_in[1];
    const float* ucf   = (const float*)d_in[2];
    const float* icf   = (const float*)d_in[3];
    const float* relw  = (const float*)d_in[4];
    const float* W1    = (const float*)d_in[5];
    const float* b1    = (const float*)d_in[6];
    const float* W2    = (const float*)d_in[7];
    const float* b2    = (const float*)d_in[8];
    const int*   eidx  = (const int*)d_in[9];
    const int*   etype = (const int*)d_in[10];
    const int*   imat  = (const int*)d_in[11];

    float* out      = (float*)d_out;
    float* out_ent  = out;
    float* out_u    = out_ent + (size_t)N_ENT * D;
    float* out_ucf  = out_u   + (size_t)N_USERS * D;
    float* out_item = out_ucf + (size_t)N_USERS * D;
    float* out_mask = out_item + (size_t)N_ITEMS * D;

    static cudaStream_t sE;
    static cudaEvent_t ev0, evE, evW, evI;
    static bool inited = false;
    if (!inited) {
        cudaStreamCreateWithFlags(&sE, cudaStreamNonBlocking);
        cudaEventCreateWithFlags(&ev0, cudaEventDisableTiming);
        cudaEventCreateWithFlags(&evE, cudaEventDisableTiming);
        cudaEventCreateWithFlags(&evW, cudaEventDisableTiming);
        cudaEventCreateWithFlags(&evI, cudaEventDisableTiming);
        inited = true;
    }

    const int T = 256;

    // fork
    cudaEventRecord(ev0, 0);
    cudaStreamWaitEvent(sE, ev0, 0);

    // ---- edge chain on sE: wkg first (iter3 prerequisite), then sort+entity ----
    zeroER_kernel<<<(N_ITEMS * N_REL + T - 1) / T, T, 0, sE>>>(W1, W2);
    histER_kernel<<<(N_EDGES + T - 1) / T, T, 0, sE>>>(eidx, etype);
    wkg_kernel<<<N_ITEMS / 16, T, 0, sE>>>(ent, relw);
    cudaEventRecord(evW, sE);
    scanA_kernel<<<PB0, T, 0, sE>>>(0);
    scanC_kernel<<<PB0, T, 0, sE>>>(0);
    scatterE_kernel<<<(N_EDGES + T - 1) / T, T, 0, sE>>>(eidx, eidx + N_EDGES, etype);
    entity_kernel<<<EBLK, T, 0, sE>>>(ent, relw, b1, b2, out_ent);

    // ---- inter chain on default ----
    zeroI_kernel<<<(N_USERS + T - 1) / T, T>>>();
    histI_kernel<<<(N_INTER + T - 1) / T, T>>>((const int2*)imat, icf);
    scanA_kernel<<<PB1 + PB2, T>>>(PB0);
    scanC_kernel<<<PB1 + PB2, T>>>(PB0);
    scatterI_kernel<<<(N_INTER + T - 1) / T, T>>>((const int2*)imat);
    cudaEventRecord(evI, 0);

    // item_agg overlaps iter3 on sE
    cudaStreamWaitEvent(sE, evI, 0);
    item_kernel<<<N_ITEMS / 8, T, 0, sE>>>(ucf, out_item);
    cudaEventRecord(evE, sE);

    // iter3 on default (waits for wkg)
    cudaStreamWaitEvent(0, evW, 0);
    iter3_kernel<<<N_USERS / 8, T>>>(user, ucf, ent, icf,
                                     out_u, out_ucf, out_mask);
    cudaStreamWaitEvent(0, evE, 0);
}

// round 17
// speedup vs baseline: 1.0409x; 1.0409x over previous
#include <cuda_runtime.h>
#include <cuda_fp16.h>

#define N_USERS   50000
#define N_ITEMS   30000
#define N_ENT     100000
#define N_REL     50
#define N_EDGES   1500000
#define N_INTER   1000000
#define D         64
#define GAMMA_F   0.1f
#define FULLMASK  0xffffffffu

#define PB0 49   // ceil(N_ENT/2048)
#define PB1 25   // ceil(N_USERS/2048)
#define PB2 15   // ceil(N_ITEMS/2048)
#define PBT (PB0 + PB1 + PB2)

// ---------------- static device scratch ----------------
__device__ int   g_bins_e[N_ENT];
__device__ int   g_bins_r[N_USERS];
__device__ int   g_bins_c[N_ITEMS];
__device__ int   g_cur_e[N_ENT];
__device__ int   g_cur_r[N_USERS];
__device__ int   g_cur_c[N_ITEMS];
__device__ int   g_eoff[N_ENT + 1];
__device__ int   g_roff[N_USERS + 1];
__device__ int   g_coff[N_ITEMS + 1];
__device__ int   g_part[PBT];
__device__ int   g_tp[N_EDGES];          // packed tail | (rel<<17)
__device__ int2  g_rc[N_INTER];          // (col, orig idx)
__device__ int   g_crow[N_INTER];
__device__ int   g_rhist[N_ITEMS * N_REL];
__device__ float g_W1t[D * D];
__device__ float g_W2t[D * D];
__device__ uint2 g_wkg_h[N_ITEMS * 16];  // fp16 wkg rows
__device__ uint2 g_icf_h[N_ITEMS * 16];  // fp16 icf rows
__device__ float g_cu[N_INTER];          // slow path only
__device__ float g_cc[N_INTER];

__device__ __forceinline__ float fsigmoid(float x) {
    return __fdividef(1.f, 1.f + __expf(-x));
}

__device__ __forceinline__ uint2 pack_h4(float a, float b, float c, float d) {
    __half2 h0 = __floats2half2_rn(a, b);
    __half2 h1 = __floats2half2_rn(c, d);
    uint2 pk;
    pk.x = *(unsigned*)&h0;
    pk.y = *(unsigned*)&h1;
    return pk;
}

// ---------------- edge chain setup ----------------
__global__ void zeroER_kernel(const float* __restrict__ W1, const float* __restrict__ W2) {
    int i = blockIdx.x * blockDim.x + threadIdx.x;
    if (i < N_ENT) g_bins_e[i] = 0;
    if (i < N_ITEMS * N_REL) g_rhist[i] = 0;
    if (i < D * D) {
        int d = i >> 6, k = i & 63;
        g_W1t[(k << 6) + d] = W1[i];
        g_W2t[(k << 6) + d] = W2[i];
    }
}

__global__ void histER_kernel(const int* __restrict__ head,
                              const int* __restrict__ etype) {
    int i = blockIdx.x * blockDim.x + threadIdx.x;
    if (i < N_EDGES) {
        int h = head[i];
        atomicAdd(&g_bins_e[h], 1);
        if (h < N_ITEMS) atomicAdd(&g_rhist[h * N_REL + etype[i]], 1);
    }
}

__global__ void scatterE_kernel(const int* __restrict__ head,
                                const int* __restrict__ tail,
                                const int* __restrict__ etype) {
    int i = blockIdx.x * blockDim.x + threadIdx.x;
    if (i < N_EDGES) {
        int h = head[i];
        int pos = atomicAdd(&g_cur_e[h], 1);
        g_tp[pos] = tail[i] | (etype[i] << 17);
    }
}

// warp handles 2 items: wkg = (hist @ relw / deg) * ent, stored fp16
__global__ void __launch_bounds__(256) wkg_kernel(
    const float* __restrict__ ent, const float* __restrict__ relw)
{
    __shared__ float sRel[N_REL * D];
    int tid = threadIdx.x;
    for (int i = tid; i < N_REL * D; i += 256) sRel[i] = relw[i];
    __syncthreads();

    int warp = tid >> 5, lane = tid & 31, hl = lane >> 4, q = lane & 15;
    int h = blockIdx.x * 16 + warp * 2 + hl;   // 1875*16 = 30000 exact
    float4 acc = make_float4(0.f, 0.f, 0.f, 0.f);
    int deg = 0;
    #pragma unroll 5
    for (int r = 0; r < N_REL; r++) {
        int cnt = g_rhist[h * N_REL + r];
        deg += cnt;
        if (cnt) {
            float fc = (float)cnt;
            float4 w = *(const float4*)&sRel[r * D + q * 4];
            acc.x += fc * w.x; acc.y += fc * w.y;
            acc.z += fc * w.z; acc.w += fc * w.w;
        }
    }
    float inv = 1.f / fmaxf((float)deg, 1.f);
    float4 kg = *(const float4*)&ent[(size_t)h * D + q * 4];
    g_wkg_h[h * 16 + q] = pack_h4(acc.x * inv * kg.x, acc.y * inv * kg.y,
                                  acc.z * inv * kg.z, acc.w * inv * kg.w);
}

// ---------------- inter chain setup ----------------
__global__ void zeroI_kernel(const float* __restrict__ icf) {
    int i = blockIdx.x * blockDim.x + threadIdx.x;
    if (i < N_USERS) g_bins_r[i] = 0;
    if (i < N_ITEMS) g_bins_c[i] = 0;
    if (i < N_ITEMS * 16) {
        float4 v = ((const float4*)icf)[i];
        g_icf_h[i] = pack_h4(v.x, v.y, v.z, v.w);
    }
}

__global__ void histI_kernel(const int2* __restrict__ imat) {
    int i = blockIdx.x * blockDim.x + threadIdx.x;
    if (i < N_INTER) {
        int2 rc = imat[i];
        atomicAdd(&g_bins_r[rc.x], 1);
        atomicAdd(&g_bins_c[rc.y], 1);
    }
}

__global__ void scatterI_kernel(const int2* __restrict__ imat) {
    int i = blockIdx.x * blockDim.x + threadIdx.x;
    if (i < N_INTER) {
        int2 rc = imat[i];
        int pr = atomicAdd(&g_cur_r[rc.x], 1);
        g_rc[pr] = make_int2(rc.y, i);
        int pc = atomicAdd(&g_cur_c[rc.y], 1);
        g_crow[pc] = rc.x;
    }
}

// ---------------- 2-phase multi-block scan ----------------
__device__ __forceinline__ void scan_map(int b, int& which, int& lb) {
    which = (b < PB0) ? 0 : (b < PB0 + PB1) ? 1 : 2;
    lb = b - ((which == 0) ? 0 : (which == 1) ? PB0 : PB0 + PB1);
}

__global__ void __launch_bounds__(256) scanA_kernel(int base_blk) {
    int b = blockIdx.x + base_blk;
    int which, lb;
    scan_map(b, which, lb);
    int n = (which == 0) ? N_ENT : (which == 1) ? N_USERS : N_ITEMS;
    const int* bins = (which == 0) ? g_bins_e : (which == 1) ? g_bins_r : g_bins_c;
    int base = lb * 2048;
    int sum = 0;
    for (int i = threadIdx.x; i < 2048; i += 256) {
        int idx = base + i;
        sum += (idx < n) ? bins[idx] : 0;
    }
    #pragma unroll
    for (int o = 16; o; o >>= 1) sum += __shfl_xor_sync(FULLMASK, sum, o);
    __shared__ int ws[8];
    int lane = threadIdx.x & 31, wid = threadIdx.x >> 5;
    if (lane == 0) ws[wid] = sum;
    __syncthreads();
    if (threadIdx.x == 0) {
        int t = 0;
        #pragma unroll
        for (int i = 0; i < 8; i++) t += ws[i];
        g_part[b] = t;
    }
}

__global__ void __launch_bounds__(256) scanC_kernel(int base_blk) {
    int b = blockIdx.x + base_blk;
    int which, lb;
    scan_map(b, which, lb);
    int n  = (which == 0) ? N_ENT : (which == 1) ? N_USERS : N_ITEMS;
    int nb = (which == 0) ? PB0   : (which == 1) ? PB1     : PB2;
    int pbase = (which == 0) ? 0  : (which == 1) ? PB0     : PB0 + PB1;
    const int* bins = (which == 0) ? g_bins_e : (which == 1) ? g_bins_r : g_bins_c;
    int* offs = (which == 0) ? g_eoff : (which == 1) ? g_roff : g_coff;
    int* cur  = (which == 0) ? g_cur_e : (which == 1) ? g_cur_r : g_cur_c;
    int base = lb * 2048;
    int lane = threadIdx.x & 31, wid = threadIdx.x >> 5;

    __shared__ int s_pref;
    if (wid == 0) {
        int p = 0;
        for (int i = lane; i < lb; i += 32) p += g_part[pbase + i];
        #pragma unroll
        for (int o = 16; o; o >>= 1) p += __shfl_xor_sync(FULLMASK, p, o);
        if (lane == 0) {
            s_pref = p;
            if (lb == nb - 1) offs[n] = p + g_part[pbase + lb];
        }
    }

    int vals[8];
    int tsum = 0;
    #pragma unroll
    for (int k = 0; k < 8; k++) {
        int idx = base + threadIdx.x * 8 + k;
        vals[k] = (idx < n) ? bins[idx] : 0;
        tsum += vals[k];
    }
    int x = tsum;
    #pragma unroll
    for (int o = 1; o < 32; o <<= 1) {
        int t = __shfl_up_sync(FULLMASK, x, o);
        if (lane >= o) x += t;
    }
    __shared__ int ws[8];
    if (lane == 31) ws[wid] = x;
    __syncthreads();
    int wpref = 0;
    for (int i = 0; i < wid; i++) wpref += ws[i];
    int acc = s_pref + wpref + x - tsum;
    #pragma unroll
    for (int k = 0; k < 8; k++) {
        int idx = base + threadIdx.x * 8 + k;
        if (idx < n) { offs[idx] = acc; cur[idx] = acc; }
        acc += vals[k];
    }
}

// ---------------- KG aggregation: 2 entities per warp ----------------
#define EBLK 6250

__global__ void __launch_bounds__(256) entity_kernel(
    const float* __restrict__ ent, const float* __restrict__ relw,
    const float* __restrict__ b1, const float* __restrict__ b2,
    float* __restrict__ out_agg)
{
    __shared__ float sRel[N_REL * D];
    __shared__ float sMA[8][2][D];
    __shared__ float sMB[8][2][D];
    int tid = threadIdx.x;
    for (int i = tid; i < N_REL * D; i += 256) sRel[i] = relw[i];
    __syncthreads();

    int warp = tid >> 5, lane = tid & 31, hl = lane >> 4, q = lane & 15;
    int h = blockIdx.x * 16 + warp * 2 + hl;
    int s = g_eoff[h], e = g_eoff[h + 1];
    bool head_item = (h < N_ITEMS);

    float4 a1 = make_float4(0.f, 0.f, 0.f, 0.f), a2 = a1;
    int c1 = 0, c2 = 0;
    #pragma unroll 2
    for (int j = s; j < e; j++) {
        int v = g_tp[j];
        int t = v & 0x1FFFF;
        int r = v >> 17;
        float4 te = *(const float4*)&ent[(size_t)t * D + q * 4];
        float4 re = *(const float4*)&sRel[r * D + q * 4];
        bool cross = head_item ^ (t < N_ITEMS);
        if (cross) {
            a1.x += te.x * re.x; a1.y += te.y * re.y;
            a1.z += te.z * re.z; a1.w += te.w * re.w; c1++;
        } else {
            a2.x += te.x + re.x; a2.y += te.y + re.y;
            a2.z += te.z + re.z; a2.w += te.w + re.w; c2++;
        }
    }
    float inv1 = 1.f / fmaxf((float)c1, 1.f);
    float inv2 = 1.f / fmaxf((float)c2, 1.f);

    *(float4*)&sMA[warp][hl][q * 4] = make_float4(a1.x * inv1, a1.y * inv1, a1.z * inv1, a1.w * inv1);
    *(float4*)&sMB[warp][hl][q * 4] = make_float4(a2.x * inv2, a2.y * inv2, a2.z * inv2, a2.w * inv2);
    __syncwarp();

    float4 o = *(const float4*)&b1[q * 4];
    float4 p = *(const float4*)&b2[q * 4];
    #pragma unroll 8
    for (int k = 0; k < D; k++) {
        float m1 = sMA[warp][hl][k];
        float m2 = sMB[warp][hl][k];
        float4 w1 = *(const float4*)&g_W1t[k * D + q * 4];
        float4 w2 = *(const float4*)&g_W2t[k * D + q * 4];
        o.x += m1 * w1.x; o.y += m1 * w1.y; o.z += m1 * w1.z; o.w += m1 * w1.w;
        p.x += m2 * w2.x; p.y += m2 * w2.y; p.z += m2 * w2.z; p.w += m2 * w2.w;
    }
    float4 r;
    r.x = (o.x >= 0.f ? o.x : 0.01f * o.x) * 0.5f + (p.x >= 0.f ? p.x : 0.01f * p.x) * 0.5f;
    r.y = (o.y >= 0.f ? o.y : 0.01f * o.y) * 0.5f + (p.y >= 0.f ? p.y : 0.01f * p.y) * 0.5f;
    r.z = (o.z >= 0.f ? o.z : 0.01f * o.z) * 0.5f + (p.z >= 0.f ? p.z : 0.01f * p.z) * 0.5f;
    r.w = (o.w >= 0.f ? o.w : 0.01f * o.w) * 0.5f + (p.w >= 0.f ? p.w : 0.01f * p.w) * 0.5f;
    *(float4*)&out_agg[(size_t)h * D + q * 4] = r;
}

// ---------------- item_agg: warp per item ----------------
__global__ void __launch_bounds__(256) item_kernel(
    const float* __restrict__ ucf0, float* __restrict__ out_item)
{
    int warp = threadIdx.x >> 5, lane = threadIdx.x & 31;
    int hl = lane >> 4, q = lane & 15;
    int it = blockIdx.x * 8 + warp;
    int s = g_coff[it], e = g_coff[it + 1];
    float4 acc = make_float4(0.f, 0.f, 0.f, 0.f);
    int j = s;
    #pragma unroll 2
    for (; j + 2 <= e; j += 2) {
        int r = g_crow[j + hl];
        float4 v = *(const float4*)&ucf0[(size_t)r * D + q * 4];
        acc.x += v.x; acc.y += v.y; acc.z += v.z; acc.w += v.w;
    }
    if (j < e && hl == 0) {
        int r = g_crow[j];
        float4 v = *(const float4*)&ucf0[(size_t)r * D + q * 4];
        acc.x += v.x; acc.y += v.y; acc.z += v.z; acc.w += v.w;
    }
    acc.x += __shfl_xor_sync(FULLMASK, acc.x, 16);
    acc.y += __shfl_xor_sync(FULLMASK, acc.y, 16);
    acc.z += __shfl_xor_sync(FULLMASK, acc.z, 16);
    acc.w += __shfl_xor_sync(FULLMASK, acc.w, 16);
    if (hl == 0) {
        float inv = 1.f / fmaxf((float)(e - s), 1.f);
        float4 r = make_float4(acc.x * inv, acc.y * inv, acc.z * inv, acc.w * inv);
        *(float4*)&out_item[(size_t)it * D + q * 4] = r;
    }
}

// ---------------- fused 3-iteration CF attention (register + smem dots) ----------------
__global__ void __launch_bounds__(256) iter3_kernel(
    const float* __restrict__ user, const float* __restrict__ ucf0,
    const float* __restrict__ ent,  const float* __restrict__ icf,
    float* __restrict__ out_u, float* __restrict__ out_ucf,
    float* __restrict__ out_mask)
{
    __shared__ float sd1[8][32];
    __shared__ float sd2[8][32];
    int warp = threadIdx.x >> 5, lane = threadIdx.x & 31;
    int hl = lane >> 4, q = lane & 15;

    int gw = blockIdx.x * 8 + warp;
    int s = g_roff[gw], e = g_roff[gw + 1];
    int deg = e - s;

    float4 u = *(const float4*)&user[(size_t)gw * D + q * 4];
    float4 c = *(const float4*)&ucf0[(size_t)gw * D + q * 4];

    if (deg <= 32) {
        // ======== FAST PATH ========
        int2 rcme = make_int2(0, 0);
        if (lane < deg) rcme = g_rc[s + lane];
        int colme = rcme.x;

        #pragma unroll 1
        for (int it = 0; it < 3; it++) {
            // ---- pass 1: dots -> smem slots ----
            for (int l0 = 0; l0 < deg; l0 += 2) {
                int a = l0 + hl;
                int aa = (a < deg) ? a : l0;
                int col = __shfl_sync(FULLMASK, colme, aa);
                uint2 wr = g_wkg_h[(size_t)col * 16 + q];
                uint2 vr = g_icf_h[(size_t)col * 16 + q];
                float2 wa = __half22float2(*(__half2*)&wr.x);
                float2 wb = __half22float2(*(__half2*)&wr.y);
                float2 va = __half22float2(*(__half2*)&vr.x);
                float2 vb = __half22float2(*(__half2*)&vr.y);
                float d1 = u.x * wa.x + u.y * wa.y + u.z * wb.x + u.w * wb.y;
                float d2 = c.x * va.x + c.y * va.y + c.z * vb.x + c.w * vb.y;
                #pragma unroll
                for (int o = 8; o; o >>= 1) {
                    d1 += __shfl_xor_sync(FULLMASK, d1, o);
                    d2 += __shfl_xor_sync(FULLMASK, d2, o);
                }
                if (q == 0 && a < deg) {
                    sd1[warp][a] = d1;
                    sd2[warp][a] = d2;
                }
            }
            __syncwarp();
            float epu = 0.f, epc = 0.f;
            if (lane < deg) {
                epu = __expf(fsigmoid(sd1[warp][lane]));
                epc = __expf(fsigmoid(sd2[warp][lane]));
            }
            float z = epu, zc = epc;
            #pragma unroll
            for (int o = 16; o; o >>= 1) {
                z  += __shfl_xor_sync(FULLMASK, z, o);
                zc += __shfl_xor_sync(FULLMASK, zc, o);
            }
            float iz  = (z  > 0.f) ? __fdividef(1.f, z)  : 0.f;
            float izc = (zc > 0.f) ? __fdividef(1.f, zc) : 0.f;
            float pn = epu * iz, qn = epc * izc;
            float m = (fabsf(fsigmoid(pn) - fsigmoid(qn)) < GAMMA_F) ? 1.f : 0.f;
            float coefu = pn * m, coefc = qn * m;
            if (it == 2 && lane < deg) out_mask[rcme.y] = m;

            // ---- pass 2: weighted sums (fp32) ----
            float4 au = make_float4(0.f, 0.f, 0.f, 0.f), ac = au;
            #pragma unroll 2
            for (int l0 = 0; l0 < deg; l0 += 2) {
                int a = l0 + hl;
                int aa = (a < deg) ? a : l0;
                int col = __shfl_sync(FULLMASK, colme, aa);
                float cu = __shfl_sync(FULLMASK, coefu, aa);
                float cc = __shfl_sync(FULLMASK, coefc, aa);
                if (a >= deg) { cu = 0.f; cc = 0.f; }
                float4 kg = *(const float4*)&ent[(size_t)col * D + q * 4];
                float4 v  = *(const float4*)&icf[(size_t)col * D + q * 4];
                au.x += cu * kg.x; au.y += cu * kg.y; au.z += cu * kg.z; au.w += cu * kg.w;
                ac.x += cc * v.x;  ac.y += cc * v.y;  ac.z += cc * v.z;  ac.w += cc * v.w;
            }
            au.x += __shfl_xor_sync(FULLMASK, au.x, 16);
            au.y += __shfl_xor_sync(FULLMASK, au.y, 16);
            au.z += __shfl_xor_sync(FULLMASK, au.z, 16);
            au.w += __shfl_xor_sync(FULLMASK, au.w, 16);
            ac.x += __shfl_xor_sync(FULLMASK, ac.x, 16);
            ac.y += __shfl_xor_sync(FULLMASK, ac.y, 16);
            ac.z += __shfl_xor_sync(FULLMASK, ac.z, 16);
            ac.w += __shfl_xor_sync(FULLMASK, ac.w, 16);

            if (it < 2) {
                float su = au.x * au.x + au.y * au.y + au.z * au.z + au.w * au.w;
                float sc = ac.x * ac.x + ac.y * ac.y + ac.z * ac.z + ac.w * ac.w;
                #pragma unroll
                for (int o = 8; o; o >>= 1) {
                    su += __shfl_xor_sync(FULLMASK, su, o);
                    sc += __shfl_xor_sync(FULLMASK, sc, o);
                }
                float inu = __fdividef(1.f, fmaxf(sqrtf(su), 1e-12f));
                float inc = __fdividef(1.f, fmaxf(sqrtf(sc), 1e-12f));
                u.x = au.x * inu; u.y = au.y * inu; u.z = au.z * inu; u.w = au.w * inu;
                c.x = ac.x * inc; c.y = ac.y * inc; c.z = ac.z * inc; c.w = ac.w * inc;
            } else if (hl == 0) {
                *(float4*)&out_u[(size_t)gw * D + q * 4]   = au;
                *(float4*)&out_ucf[(size_t)gw * D + q * 4] = ac;
            }
            __syncwarp();
        }
        return;
    }

    // ======== SLOW PATH (deg > 32) ========
    #pragma unroll 1
    for (int it = 0; it < 3; it++) {
        float z = 0.f, zc = 0.f;
        int j = s;
        for (; j + 2 <= e; j += 2) {
            int col = g_rc[j + hl].x;
            uint2 wr = g_wkg_h[(size_t)col * 16 + q];
            uint2 vr = g_icf_h[(size_t)col * 16 + q];
            float2 wa = __half22float2(*(__half2*)&wr.x);
            float2 wb = __half22float2(*(__half2*)&wr.y);
            float2 va = __half22float2(*(__half2*)&vr.x);
            float2 vb = __half22float2(*(__half2*)&vr.y);
            float d1 = u.x * wa.x + u.y * wa.y + u.z * wb.x + u.w * wb.y;
            float d2 = c.x * va.x + c.y * va.y + c.z * vb.x + c.w * vb.y;
            #pragma unroll
            for (int o = 8; o; o >>= 1) {
                d1 += __shfl_xor_sync(FULLMASK, d1, o);
                d2 += __shfl_xor_sync(FULLMASK, d2, o);
            }
            if (q == 0) {
                float ep = __expf(fsigmoid(d1));
                float eq = __expf(fsigmoid(d2));
                z += ep; zc += eq;
                g_cu[j + hl] = ep;
                g_cc[j + hl] = eq;
            }
        }
        if (j < e) {
            int col = g_rc[j].x;
            uint2 wr = g_wkg_h[(size_t)col * 16 + q];
            uint2 vr = g_icf_h[(size_t)col * 16 + q];
            float2 wa = __half22float2(*(__half2*)&wr.x);
            float2 wb = __half22float2(*(__half2*)&wr.y);
            float2 va = __half22float2(*(__half2*)&vr.x);
            float2 vb = __half22float2(*(__half2*)&vr.y);
            float d1 = u.x * wa.x + u.y * wa.y + u.z * wb.x + u.w * wb.y;
            float d2 = c.x * va.x + c.y * va.y + c.z * vb.x + c.w * vb.y;
            #pragma unroll
            for (int o = 8; o; o >>= 1) {
                d1 += __shfl_xor_sync(FULLMASK, d1, o);
                d2 += __shfl_xor_sync(FULLMASK, d2, o);
            }
            if (lane == 0) {
                float ep = __expf(fsigmoid(d1));
                float eq = __expf(fsigmoid(d2));
                z += ep; zc += eq;
                g_cu[j] = ep;
                g_cc[j] = eq;
            }
        }
        __syncwarp();
        #pragma unroll
        for (int o = 16; o; o >>= 1) {
            z  += __shfl_xor_sync(FULLMASK, z, o);
            zc += __shfl_xor_sync(FULLMASK, zc, o);
        }
        float iz  = (z  > 0.f) ? __fdividef(1.f, z)  : 0.f;
        float izc = (zc > 0.f) ? __fdividef(1.f, zc) : 0.f;

        for (int jj = s + lane; jj < e; jj += 32) {
            float pn = g_cu[jj] * iz;
            float qn = g_cc[jj] * izc;
            float m = (fabsf(fsigmoid(pn) - fsigmoid(qn)) < GAMMA_F) ? 1.f : 0.f;
            if (it == 2) out_mask[g_rc[jj].y] = m;
            g_cu[jj] = pn * m;
            g_cc[jj] = qn * m;
        }
        __syncwarp();

        float4 au = make_float4(0.f, 0.f, 0.f, 0.f), ac = au;
        j = s;
        for (; j + 2 <= e; j += 2) {
            int jj = j + hl;
            int col = g_rc[jj].x;
            float cu = g_cu[jj], cc = g_cc[jj];
            float4 kg = *(const float4*)&ent[(size_t)col * D + q * 4];
            float4 v  = *(const float4*)&icf[(size_t)col * D + q * 4];
            au.x += cu * kg.x; au.y += cu * kg.y; au.z += cu * kg.z; au.w += cu * kg.w;
            ac.x += cc * v.x;  ac.y += cc * v.y;  ac.z += cc * v.z;  ac.w += cc * v.w;
        }
        if (j < e && hl == 0) {
            int col = g_rc[j].x;
            float cu = g_cu[j], cc = g_cc[j];
            float4 kg = *(const float4*)&ent[(size_t)col * D + q * 4];
            float4 v  = *(const float4*)&icf[(size_t)col * D + q * 4];
            au.x += cu * kg.x; au.y += cu * kg.y; au.z += cu * kg.z; au.w += cu * kg.w;
            ac.x += cc * v.x;  ac.y += cc * v.y;  ac.z += cc * v.z;  ac.w += cc * v.w;
        }
        au.x += __shfl_xor_sync(FULLMASK, au.x, 16);
        au.y += __shfl_xor_sync(FULLMASK, au.y, 16);
        au.z += __shfl_xor_sync(FULLMASK, au.z, 16);
        au.w += __shfl_xor_sync(FULLMASK, au.w, 16);
        ac.x += __shfl_xor_sync(FULLMASK, ac.x, 16);
        ac.y += __shfl_xor_sync(FULLMASK, ac.y, 16);
        ac.z += __shfl_xor_sync(FULLMASK, ac.z, 16);
        ac.w += __shfl_xor_sync(FULLMASK, ac.w, 16);

        if (it < 2) {
            float su = au.x * au.x + au.y * au.y + au.z * au.z + au.w * au.w;
            float sc = ac.x * ac.x + ac.y * ac.y + ac.z * ac.z + ac.w * ac.w;
            #pragma unroll
            for (int o = 8; o; o >>= 1) {
                su += __shfl_xor_sync(FULLMASK, su, o);
                sc += __shfl_xor_sync(FULLMASK, sc, o);
            }
            float inu = __fdividef(1.f, fmaxf(sqrtf(su), 1e-12f));
            float inc = __fdividef(1.f, fmaxf(sqrtf(sc), 1e-12f));
            u.x = au.x * inu; u.y = au.y * inu; u.z = au.z * inu; u.w = au.w * inu;
            c.x = ac.x * inc; c.y = ac.y * inc; c.z = ac.z * inc; c.w = ac.w * inc;
        } else if (hl == 0) {
            *(float4*)&out_u[(size_t)gw * D + q * 4]   = au;
            *(float4*)&out_ucf[(size_t)gw * D + q * 4] = ac;
        }
        __syncwarp();
    }
}

// ---------------- launch: dependency-ordered fork (R9 structure) ----------------
extern "C" void kernel_launch(void* const* d_in, const int* in_sizes, int n_in,
                              void* d_out, int out_size) {
    const float* ent   = (const float*)d_in[0];
    const float* user  = (const float*)d_in[1];
    const float* ucf   = (const float*)d_in[2];
    const float* icf   = (const float*)d_in[3];
    const float* relw  = (const float*)d_in[4];
    const float* W1    = (const float*)d_in[5];
    const float* b1    = (const float*)d_in[6];
    const float* W2    = (const float*)d_in[7];
    const float* b2    = (const float*)d_in[8];
    const int*   eidx  = (const int*)d_in[9];
    const int*   etype = (const int*)d_in[10];
    const int*   imat  = (const int*)d_in[11];

    float* out      = (float*)d_out;
    float* out_ent  = out;
    float* out_u    = out_ent + (size_t)N_ENT * D;
    float* out_ucf  = out_u   + (size_t)N_USERS * D;
    float* out_item = out_ucf + (size_t)N_USERS * D;
    float* out_mask = out_item + (size_t)N_ITEMS * D;

    static cudaStream_t sE;
    static cudaEvent_t ev0, evE, evW, evI;
    static bool inited = false;
    if (!inited) {
        cudaStreamCreateWithFlags(&sE, cudaStreamNonBlocking);
        cudaEventCreateWithFlags(&ev0, cudaEventDisableTiming);
        cudaEventCreateWithFlags(&evE, cudaEventDisableTiming);
        cudaEventCreateWithFlags(&evW, cudaEventDisableTiming);
        cudaEventCreateWithFlags(&evI, cudaEventDisableTiming);
        inited = true;
    }

    const int T = 256;

    // fork
    cudaEventRecord(ev0, 0);
    cudaStreamWaitEvent(sE, ev0, 0);

    // ---- edge chain on sE: wkg first (iter3 prerequisite), then sort+entity ----
    zeroER_kernel<<<(N_ITEMS * N_REL + T - 1) / T, T, 0, sE>>>(W1, W2);
    histER_kernel<<<(N_EDGES + T - 1) / T, T, 0, sE>>>(eidx, etype);
    wkg_kernel<<<N_ITEMS / 16, T, 0, sE>>>(ent, relw);
    cudaEventRecord(evW, sE);
    scanA_kernel<<<PB0, T, 0, sE>>>(0);
    scanC_kernel<<<PB0, T, 0, sE>>>(0);
    scatterE_kernel<<<(N_EDGES + T - 1) / T, T, 0, sE>>>(eidx, eidx + N_EDGES, etype);
    entity_kernel<<<EBLK, T, 0, sE>>>(ent, relw, b1, b2, out_ent);

    // ---- inter chain on default ----
    zeroI_kernel<<<(N_ITEMS * 16 + T - 1) / T, T>>>(icf);
    histI_kernel<<<(N_INTER + T - 1) / T, T>>>((const int2*)imat);
    scanA_kernel<<<PB1 + PB2, T>>>(PB0);
    scanC_kernel<<<PB1 + PB2, T>>>(PB0);
    scatterI_kernel<<<(N_INTER + T - 1) / T, T>>>((const int2*)imat);
    cudaEventRecord(evI, 0);

    // item_agg overlaps iter3 on sE
    cudaStreamWaitEvent(sE, evI, 0);
    item_kernel<<<N_ITEMS / 8, T, 0, sE>>>(ucf, out_item);
    cudaEventRecord(evE, sE);

    // iter3 on default (waits for wkg)
    cudaStreamWaitEvent(0, evW, 0);
    iter3_kernel<<<N_USERS / 8, T>>>(user, ucf, ent, icf,
                                     out_u, out_ucf, out_mask);
    cudaStreamWaitEvent(0, evE, 0);
}